// round 12
// baseline (speedup 1.0000x reference)
#include <cuda_runtime.h>
#include <cuda_fp16.h>
#include <cstddef>
#include <cstdint>

#define NN 50000
#define NE 800000
#define DIN 128
#define DHID 128
#define DOUT 64

// ---------------- scratch (__device__ globals; no allocation) ----------------
__device__ __half g_xw1[(size_t)NN * DHID];   // fp16 x@W1 (RAW)
__device__ __half g_agg1[(size_t)NN * DHID];  // fp16 relu(gcn1)
__device__ __half g_xw2[(size_t)NN * DOUT];   // fp16 (agg1@W2)*dis
__device__ float  g_dis[NN];
__device__ int    g_cnt[NN];    // zero-init; restored to 0 inside k_csr
__device__ int    g_cur[NN];
__device__ int    g_off[NN + 1];
__device__ int    g_esrc[NE];
__device__ int    g_bsum[64];
__device__ int    g_bar[3];     // grid-barrier counters; self-reset
__device__ int    g_exit;       // exit counter; self-reset

// ---------------- fused CSR build: one persistent kernel ----------------
__device__ __forceinline__ void gridbar(int slot, int nb) {
    __syncthreads();
    if (threadIdx.x == 0) {
        __threadfence();
        atomicAdd(&g_bar[slot], 1);
        volatile int* p = &g_bar[slot];
        while (*p < nb) {}
        __threadfence();
    }
    __syncthreads();
}

__global__ void __launch_bounds__(1024, 1)
k_csr(const int* __restrict__ src, const int* __restrict__ dst,
      int n, int e, int nb)
{
    const int tid  = threadIdx.x;
    const int bid  = blockIdx.x;
    const int gtid = bid * 1024 + tid;
    const int NTH  = nb * 1024;
    const int e4   = e / 4;

    // ---- phase 1: histogram ----
    for (int g = gtid; g < e4; g += NTH) {
        int4 d = *(const int4*)(dst + g * 4);
        atomicAdd(&g_cnt[d.x], 1);
        atomicAdd(&g_cnt[d.y], 1);
        atomicAdd(&g_cnt[d.z], 1);
        atomicAdd(&g_cnt[d.w], 1);
    }
    for (int t = e4 * 4 + gtid; t < e; t += NTH) atomicAdd(&g_cnt[dst[t]], 1);

    gridbar(0, nb);

    // ---- phase 2a: block-local exclusive scan of 1024 counts ----
    __shared__ int warpsum[32];
    __shared__ int s_pre, s_tot;
    const int lane = tid & 31, wid = tid >> 5;
    int i = gtid;
    int v = (i < n) ? g_cnt[i] : 0;
    int x = v;
#pragma unroll
    for (int o = 1; o < 32; o <<= 1) {
        int t = __shfl_up_sync(0xFFFFFFFFu, x, o);
        if (lane >= o) x += t;
    }
    if (lane == 31) warpsum[wid] = x;
    __syncthreads();
    if (wid == 0) {
        int w = warpsum[lane];
#pragma unroll
        for (int o = 1; o < 32; o <<= 1) {
            int t = __shfl_up_sync(0xFFFFFFFFu, w, o);
            if (lane >= o) w += t;
        }
        warpsum[lane] = w;
    }
    __syncthreads();
    int warpbase = (wid == 0) ? 0 : warpsum[wid - 1];
    int local = warpbase + x - v;
    if (tid == 1023) g_bsum[bid] = warpsum[31];

    gridbar(1, nb);

    // ---- phase 2b: prefix over block sums; offsets, cursors, dis ----
    if (tid < 32) {
        int i0 = 2 * lane, i1 = 2 * lane + 1;
        int v0 = (i0 < nb) ? g_bsum[i0] : 0;
        int v1 = (i1 < nb) ? g_bsum[i1] : 0;
        int p = ((i0 < bid) ? v0 : 0) + ((i1 < bid) ? v1 : 0);
        int t = v0 + v1;
#pragma unroll
        for (int o = 16; o > 0; o >>= 1) {
            p += __shfl_down_sync(0xFFFFFFFFu, p, o);
            t += __shfl_down_sync(0xFFFFFFFFu, t, o);
        }
        if (lane == 0) { s_pre = p; s_tot = t; }
    }
    __syncthreads();
    if (i < n) {
        int o = local + s_pre;
        g_off[i] = o;
        g_cur[i] = o;
        g_dis[i] = rsqrtf((float)v + 1.0f);
        g_cnt[i] = 0;                        // restore for next replay
    }
    if (bid == nb - 1 && tid == 0) g_off[n] = s_tot;

    gridbar(2, nb);

    // ---- phase 3: fill edge lists ----
    for (int g = gtid; g < e4; g += NTH) {
        int4 d = *(const int4*)(dst + g * 4);
        int4 s = *(const int4*)(src + g * 4);
        int p0 = atomicAdd(&g_cur[d.x], 1);
        int p1 = atomicAdd(&g_cur[d.y], 1);
        int p2 = atomicAdd(&g_cur[d.z], 1);
        int p3 = atomicAdd(&g_cur[d.w], 1);
        g_esrc[p0] = s.x;
        g_esrc[p1] = s.y;
        g_esrc[p2] = s.z;
        g_esrc[p3] = s.w;
    }
    for (int t = e4 * 4 + gtid; t < e; t += NTH) {
        int p = atomicAdd(&g_cur[dst[t]], 1);
        g_esrc[p] = src[t];
    }

    // ---- exit: last block resets barrier state for next replay ----
    __syncthreads();
    if (tid == 0) {
        int ve = atomicAdd(&g_exit, 1);
        if (ve == nb - 1) {
            g_bar[0] = 0; g_bar[1] = 0; g_bar[2] = 0; g_exit = 0;
            __threadfence();
        }
    }
}

// ---------------- HMMA helpers ----------------
__device__ __forceinline__ void ldsm_x4(uint32_t& r0, uint32_t& r1,
                                        uint32_t& r2, uint32_t& r3, uint32_t addr) {
    asm volatile("ldmatrix.sync.aligned.m8n8.x4.shared.b16 {%0,%1,%2,%3}, [%4];"
                 : "=r"(r0), "=r"(r1), "=r"(r2), "=r"(r3) : "r"(addr));
}
__device__ __forceinline__ void ldsm_x2t(uint32_t& r0, uint32_t& r1, uint32_t addr) {
    asm volatile("ldmatrix.sync.aligned.m8n8.x2.trans.shared.b16 {%0,%1}, [%2];"
                 : "=r"(r0), "=r"(r1) : "r"(addr));
}
__device__ __forceinline__ void mma16816(float* d, const uint32_t* a, const uint32_t* b) {
    asm volatile(
        "mma.sync.aligned.m16n8k16.row.col.f32.f16.f16.f32 "
        "{%0,%1,%2,%3}, {%4,%5,%6,%7}, {%8,%9}, {%0,%1,%2,%3};"
        : "+f"(d[0]), "+f"(d[1]), "+f"(d[2]), "+f"(d[3])
        : "r"(a[0]), "r"(a[1]), "r"(a[2]), "r"(a[3]), "r"(b[0]), "r"(b[1]));
}

// ---------------- HMMA GEMM: XWS(half) = (A @ W) [* dis[row]] ----------------
// K fixed = 128. BM=128, BN = full N (128 or 64). row0 = row_base + blk*128.
template <int BN, bool A_HALF, bool SCALE_DIS>
__global__ void __launch_bounds__(256, 2)
gemm_hmma(const void* __restrict__ Ap, const float* __restrict__ W,
          __half* __restrict__ XWS, int M, int row_base)
{
    constexpr int KK = 128, BM = 128;
    constexpr int LDA = KK + 8;
    constexpr int LDB = BN + 8;
    constexpr int NT  = BN / 32;

    extern __shared__ __half smh[];
    __half* As = smh;
    __half* Bs = smh + BM * LDA;

    const int tid  = threadIdx.x;
    const int lane = tid & 31;
    const int wid  = tid >> 5;
    const int row0 = row_base + blockIdx.x * BM;
    const int wm   = (wid & 1) * 64;
    const int wn   = (wid >> 1) * (BN / 4);

    if (A_HALF) {
        const __half* A = (const __half*)Ap;
#pragma unroll
        for (int l = 0; l < 8; l++) {
            int idx = tid + l * 256;
            int r   = idx >> 4;
            int c8  = (idx & 15) * 8;
            uint4 v = make_uint4(0, 0, 0, 0);
            int gr = row0 + r;
            if (gr < M) v = *(const uint4*)(A + (size_t)gr * KK + c8);
            *(uint4*)(As + r * LDA + c8) = v;
        }
    } else {
        const float* A = (const float*)Ap;
#pragma unroll
        for (int l = 0; l < 16; l++) {
            int idx = tid + l * 256;
            int r   = idx >> 5;
            int c4  = (idx & 31) * 4;
            float4 av = make_float4(0.f, 0.f, 0.f, 0.f);
            int gr = row0 + r;
            if (gr < M) av = *(const float4*)(A + (size_t)gr * KK + c4);
            __half2 h0 = __floats2half2_rn(av.x, av.y);
            __half2 h1 = __floats2half2_rn(av.z, av.w);
            uint2 u;
            u.x = *(uint32_t*)&h0;
            u.y = *(uint32_t*)&h1;
            *(uint2*)(As + r * LDA + c4) = u;
        }
    }
#pragma unroll
    for (int l = 0; l < (KK * BN / 4) / 256; l++) {
        int idx = tid + l * 256;
        int r   = idx / (BN / 4);
        int c4  = (idx % (BN / 4)) * 4;
        float4 bv = *(const float4*)(W + (size_t)r * BN + c4);
        __half2 h0 = __floats2half2_rn(bv.x, bv.y);
        __half2 h1 = __floats2half2_rn(bv.z, bv.w);
        uint2 u;
        u.x = *(uint32_t*)&h0;
        u.y = *(uint32_t*)&h1;
        *(uint2*)(Bs + r * LDB + c4) = u;
    }
    __syncthreads();

    const uint32_t aBase = (uint32_t)__cvta_generic_to_shared(As);
    const uint32_t bBase = (uint32_t)__cvta_generic_to_shared(Bs);

    float acc[4][NT][4];
#pragma unroll
    for (int mt = 0; mt < 4; mt++)
#pragma unroll
        for (int nt = 0; nt < NT; nt++)
#pragma unroll
            for (int q = 0; q < 4; q++) acc[mt][nt][q] = 0.0f;

#pragma unroll
    for (int ks = 0; ks < 8; ks++) {
        const int kb = ks * 16;
        uint32_t af[4][4];
#pragma unroll
        for (int mt = 0; mt < 4; mt++) {
            uint32_t addr = aBase +
                ((wm + mt * 16 + (lane & 15)) * LDA + kb + (lane >> 4) * 8) * 2;
            ldsm_x4(af[mt][0], af[mt][1], af[mt][2], af[mt][3], addr);
        }
        uint32_t bf[NT][2];
#pragma unroll
        for (int nt = 0; nt < NT; nt++) {
            uint32_t addr = bBase + ((kb + (lane & 15)) * LDB + wn + nt * 8) * 2;
            ldsm_x2t(bf[nt][0], bf[nt][1], addr);
        }
#pragma unroll
        for (int mt = 0; mt < 4; mt++)
#pragma unroll
            for (int nt = 0; nt < NT; nt++)
                mma16816(acc[mt][nt], af[mt], bf[nt]);
    }

    const int gid = lane >> 2, qid = lane & 3;
#pragma unroll
    for (int mt = 0; mt < 4; mt++) {
        int r0 = row0 + wm + mt * 16 + gid;
        int r1 = r0 + 8;
        float s0 = 1.0f, s1 = 1.0f;
        if (SCALE_DIS) {
            if (r0 < M) s0 = g_dis[r0];
            if (r1 < M) s1 = g_dis[r1];
        }
#pragma unroll
        for (int nt = 0; nt < NT; nt++) {
            int c = wn + nt * 8 + qid * 2;
            if (r0 < M) {
                __half2 h = __floats2half2_rn(acc[mt][nt][0] * s0, acc[mt][nt][1] * s0);
                *(uint32_t*)(XWS + (size_t)r0 * BN + c) = *(uint32_t*)&h;
            }
            if (r1 < M) {
                __half2 h = __floats2half2_rn(acc[mt][nt][2] * s1, acc[mt][nt][3] * s1);
                *(uint32_t*)(XWS + (size_t)r1 * BN + c) = *(uint32_t*)&h;
            }
        }
    }
}

// ---------------- CSR aggregation, D=128 (half xw): one warp per node -------
// agg1(half) = relu( dis*(self + sum xw[s]*dis[s]) + bias ), nodes [base, end)
__global__ void agg128h(const __half* __restrict__ xw,
                        const float* __restrict__ bias,
                        __half* __restrict__ out, int node_base, int node_end)
{
    int w = node_base + ((blockIdx.x * blockDim.x + threadIdx.x) >> 5);
    int lane = threadIdx.x & 31;
    if (w >= node_end) return;
    int beg = g_off[w], end = g_off[w + 1];
    float dd = g_dis[w];

    uint2 us = *(const uint2*)(xw + (size_t)w * 128 + lane * 4);
    float2 s0 = __half22float2(*(__half2*)&us.x);
    float2 s1 = __half22float2(*(__half2*)&us.y);
    float4 acc = make_float4(s0.x * dd, s0.y * dd, s1.x * dd, s1.y * dd);

    int j = beg;
    for (; j + 4 <= end; j += 4) {
        int e0 = g_esrc[j], e1 = g_esrc[j + 1], e2 = g_esrc[j + 2], e3 = g_esrc[j + 3];
        float n0 = g_dis[e0], n1 = g_dis[e1], n2 = g_dis[e2], n3 = g_dis[e3];
        uint2 u0 = *(const uint2*)(xw + (size_t)e0 * 128 + lane * 4);
        uint2 u1 = *(const uint2*)(xw + (size_t)e1 * 128 + lane * 4);
        uint2 u2 = *(const uint2*)(xw + (size_t)e2 * 128 + lane * 4);
        uint2 u3 = *(const uint2*)(xw + (size_t)e3 * 128 + lane * 4);
        float2 a0 = __half22float2(*(__half2*)&u0.x), b0 = __half22float2(*(__half2*)&u0.y);
        float2 a1 = __half22float2(*(__half2*)&u1.x), b1 = __half22float2(*(__half2*)&u1.y);
        float2 a2 = __half22float2(*(__half2*)&u2.x), b2 = __half22float2(*(__half2*)&u2.y);
        float2 a3 = __half22float2(*(__half2*)&u3.x), b3 = __half22float2(*(__half2*)&u3.y);
        acc.x += a0.x * n0 + a1.x * n1 + a2.x * n2 + a3.x * n3;
        acc.y += a0.y * n0 + a1.y * n1 + a2.y * n2 + a3.y * n3;
        acc.z += b0.x * n0 + b1.x * n1 + b2.x * n2 + b3.x * n3;
        acc.w += b0.y * n0 + b1.y * n1 + b2.y * n2 + b3.y * n3;
    }
    for (; j < end; j++) {
        int s = g_esrc[j];
        float ns = g_dis[s];
        uint2 u = *(const uint2*)(xw + (size_t)s * 128 + lane * 4);
        float2 a = __half22float2(*(__half2*)&u.x);
        float2 b = __half22float2(*(__half2*)&u.y);
        acc.x += a.x * ns; acc.y += a.y * ns; acc.z += b.x * ns; acc.w += b.y * ns;
    }
    float4 bv = *(const float4*)(bias + lane * 4);
    __half2 h0 = __floats2half2_rn(fmaxf(acc.x * dd + bv.x, 0.0f),
                                   fmaxf(acc.y * dd + bv.y, 0.0f));
    __half2 h1 = __floats2half2_rn(fmaxf(acc.z * dd + bv.z, 0.0f),
                                   fmaxf(acc.w * dd + bv.w, 0.0f));
    uint2 o;
    o.x = *(uint32_t*)&h0;
    o.y = *(uint32_t*)&h1;
    *(uint2*)(out + (size_t)w * 128 + lane * 4) = o;
}

// ---------------- CSR aggregation, D=64 (half xws pre-scaled) ---------------
__global__ void agg64h(const __half* __restrict__ xws,
                       const float* __restrict__ bias,
                       float* __restrict__ out, int n)
{
    int w = (blockIdx.x * blockDim.x + threadIdx.x) >> 5;
    int lane = threadIdx.x & 31;
    if (w >= n) return;
    int beg = g_off[w], end = g_off[w + 1];
    float dd = g_dis[w];

    float2 acc = __half22float2(*(const __half2*)(xws + (size_t)w * 64 + lane * 2));

    int j = beg;
    for (; j + 4 <= end; j += 4) {
        int e0 = g_esrc[j], e1 = g_esrc[j + 1], e2 = g_esrc[j + 2], e3 = g_esrc[j + 3];
        float2 v0 = __half22float2(*(const __half2*)(xws + (size_t)e0 * 64 + lane * 2));
        float2 v1 = __half22float2(*(const __half2*)(xws + (size_t)e1 * 64 + lane * 2));
        float2 v2 = __half22float2(*(const __half2*)(xws + (size_t)e2 * 64 + lane * 2));
        float2 v3 = __half22float2(*(const __half2*)(xws + (size_t)e3 * 64 + lane * 2));
        acc.x += v0.x + v1.x + v2.x + v3.x;
        acc.y += v0.y + v1.y + v2.y + v3.y;
    }
    for (; j < end; j++) {
        int s = g_esrc[j];
        float2 v = __half22float2(*(const __half2*)(xws + (size_t)s * 64 + lane * 2));
        acc.x += v.x; acc.y += v.y;
    }
    float2 b = *(const float2*)(bias + lane * 2);
    acc.x = acc.x * dd + b.x;
    acc.y = acc.y * dd + b.y;
    *(float2*)(out + (size_t)w * 64 + lane * 2) = acc;
}

extern "C" void kernel_launch(void* const* d_in, const int* in_sizes, int n_in,
                              void* d_out, int out_size)
{
    const float* x  = (const float*)d_in[0];
    const int*   ei = (const int*)  d_in[1];
    const float* W1 = (const float*)d_in[2];
    const float* b1 = (const float*)d_in[3];
    const float* W2 = (const float*)d_in[4];
    const float* b2 = (const float*)d_in[5];
    float* out = (float*)d_out;

    const int N = in_sizes[0] / DIN;   // 50000
    const int E = in_sizes[1] / 2;     // 800000
    const int* src = ei;
    const int* dst = ei + E;

    __half *xw1, *agg1, *xw2;
    cudaGetSymbolAddress((void**)&xw1,  g_xw1);
    cudaGetSymbolAddress((void**)&agg1, g_agg1);
    cudaGetSymbolAddress((void**)&xw2,  g_xw2);

    constexpr int SMEM1 = (128 * 136 + 128 * 136) * 2;   // 69632 B
    constexpr int SMEM2 = (128 * 136 + 128 * 72) * 2;    // 53248 B

    static cudaStream_t s_side = nullptr;
    static cudaEvent_t  s_fork = nullptr, s_join = nullptr;
    static cudaEvent_t  s_c0 = nullptr, s_g2a = nullptr;
    if (s_side == nullptr) {
        cudaStreamCreateWithFlags(&s_side, cudaStreamNonBlocking);
        cudaEventCreateWithFlags(&s_fork, cudaEventDisableTiming);
        cudaEventCreateWithFlags(&s_join, cudaEventDisableTiming);
        cudaEventCreateWithFlags(&s_c0,   cudaEventDisableTiming);
        cudaEventCreateWithFlags(&s_g2a,  cudaEventDisableTiming);
        cudaFuncSetAttribute((const void*)gemm_hmma<128, false, false>,
                             cudaFuncAttributeMaxDynamicSharedMemorySize, SMEM1);
        cudaFuncSetAttribute((const void*)gemm_hmma<64, true, true>,
                             cudaFuncAttributeMaxDynamicSharedMemorySize, SMEM2);
    }

    const int nb = (N + 1023) / 1024;        // 49
    const int gemm_grid = (N + 127) / 128;   // 391
    const int M0 = (gemm_grid / 2) * 128;    // 25088 (chunk A rows)

    // ---- fork: fused CSR build on side stream, GEMM1 on main stream ----
    cudaEventRecord(s_fork, 0);
    cudaStreamWaitEvent(s_side, s_fork, 0);
    k_csr<<<nb, 1024, 0, s_side>>>(src, dst, N, E, nb);
    cudaEventRecord(s_join, s_side);

    // main: layer-1 HMMA GEMM (graph-independent)
    gemm_hmma<128, false, false><<<gemm_grid, 256, SMEM1>>>(x, W1, xw1, N, 0);

    cudaStreamWaitEvent(0, s_join, 0);

    // layer 1 aggregation chunk 0 (nodes [0, M0))
    agg128h<<<(M0 * 32 + 255) / 256, 256>>>(xw1, b1, agg1, 0, M0);
    cudaEventRecord(s_c0, 0);

    // side: gemm2 chunk A (rows [0, M0)) overlapping agg128h chunk 1
    cudaStreamWaitEvent(s_side, s_c0, 0);
    gemm_hmma<64, true, true><<<M0 / 128, 256, SMEM2, s_side>>>(agg1, W2, xw2, M0, 0);
    cudaEventRecord(s_g2a, s_side);

    // main: agg128h chunk 1 (nodes [M0, N)), then gemm2 chunk B
    agg128h<<<((N - M0) * 32 + 255) / 256, 256>>>(xw1, b1, agg1, M0, N);
    gemm_hmma<64, true, true><<<(N - M0 + 127) / 128, 256, SMEM2>>>(agg1, W2, xw2, N, M0);

    // join gemm2 chunk A, then final aggregation
    cudaStreamWaitEvent(0, s_g2a, 0);
    agg64h<<<(N * 32 + 255) / 256, 256>>>(xw2, b2, out, N);
}